// round 4
// baseline (speedup 1.0000x reference)
#include <cuda_runtime.h>
#include <cstdint>

#define W_DIM   21504
#define NSEG    64
#define NELEM   8192
#define TILE_R  64
#define MAX_TILES 192     // sum(ceil(c/64)) <= 8192/64 + 64 = 192
#define TPB     256
#define RPAD    66        // even -> row pairs 8B-aligned in smem

typedef unsigned long long u64;

// ---------------- device globals ----------------
__device__ int  d_starts[NSEG + 1];
__device__ int2 d_tiles[MAX_TILES];   // {row_start, segment}
__device__ int  d_ntiles;

// ---------------- packed f32x2 helpers ----------------
__device__ __forceinline__ u64 pack2(float a) {
    u64 r; asm("mov.b64 %0, {%1, %1};" : "=l"(r) : "f"(a)); return r;
}
__device__ __forceinline__ u64 fma2(u64 a, u64 b, u64 c) {
    u64 d; asm("fma.rn.f32x2 %0, %1, %2, %3;" : "=l"(d) : "l"(a), "l"(b), "l"(c));
    return d;
}
__device__ __forceinline__ u64 lds64(unsigned a) {
    u64 v; asm volatile("ld.shared.b64 %0, [%1];" : "=l"(v) : "r"(a)); return v;
}
__device__ __forceinline__ float4 lds128(unsigned a) {
    float4 v;
    asm volatile("ld.shared.v4.f32 {%0,%1,%2,%3}, [%4];"
                 : "=f"(v.x), "=f"(v.y), "=f"(v.z), "=f"(v.w) : "r"(a));
    return v;
}
__device__ __forceinline__ void unpack2(u64 v, float& lo, float& hi) {
    asm("mov.b64 {%0, %1}, %2;" : "=f"(lo), "=f"(hi) : "l"(v));
}

// ---------------- prekernel: parallel scan + tile list ----------------
__global__ void seg_kernel(const int* __restrict__ counts) {
    __shared__ int wsum[2], wtsum[2];
    const int t  = threadIdx.x;           // 64 threads
    const int c  = counts[t];
    const int nt = (c + TILE_R - 1) >> 6;
    int sc = c, st = nt;
    #pragma unroll
    for (int d = 1; d < 32; d <<= 1) {
        int a = __shfl_up_sync(0xffffffffu, sc, d);
        int b = __shfl_up_sync(0xffffffffu, st, d);
        if ((t & 31) >= d) { sc += a; st += b; }
    }
    if ((t & 31) == 31) { wsum[t >> 5] = sc; wtsum[t >> 5] = st; }
    __syncthreads();
    if (t >= 32) { sc += wsum[0]; st += wtsum[0]; }
    const int startc = sc - c;
    const int startt = st - nt;
    d_starts[t] = startc;
    if (t == NSEG - 1) { d_starts[NSEG] = sc; d_ntiles = st; }
    for (int k = 0; k < nt; k++)
        d_tiles[startt + k] = make_int2(startc + TILE_R * k, t);
}

// ---------------- main compute ----------------
// Per tile (64 rows, segment g): y[r,o,i] = sum_m x[r,m,i] * (coeff*w[g,WOFF+m*MUL+o])
// x staged transposed [channel][row]; w staged pre-scaled in smem.
template <int MUL, int DIM, int OPT, int WOFF>
__device__ __forceinline__ void run_irrep(const float* __restrict__ x,
                                          const float* __restrict__ w,
                                          float* __restrict__ y,
                                          int tile, float coeff,
                                          float* xs) {
    if (tile >= d_ntiles) return;
    const int2 tt  = d_tiles[tile];
    const int row0 = tt.x;
    const int g    = tt.y;
    int nrows = d_starts[g + 1] - row0;
    if (nrows > TILE_R) nrows = TILE_R;

    constexpr int CH = MUL * DIM;
    float* wsm = xs + CH * RPAD;          // 16B-aligned for all irreps

    // ---- stage x tile transposed ----
    const float* xt = x + (size_t)row0 * CH;
    #pragma unroll 4
    for (int e = threadIdx.x; e < TILE_R * CH; e += TPB) {
        int r = e / CH;
        int c = e - r * CH;
        xs[c * RPAD + r] = (r < nrows) ? xt[e] : 0.f;
    }
    // ---- stage weight tile, pre-scaled by coeff ----
    const float4* wrow = reinterpret_cast<const float4*>(w + (size_t)g * W_DIM + WOFF);
    float4* wd = reinterpret_cast<float4*>(wsm);
    #pragma unroll 4
    for (int j = threadIdx.x; j < MUL * MUL / 4; j += TPB) {
        float4 v = wrow[j];
        wd[j] = make_float4(v.x * coeff, v.y * coeff, v.z * coeff, v.w * coeff);
    }
    __syncthreads();

    constexpr int NO  = MUL / OPT;
    constexpr int NRG = TPB / NO;
    constexpr int RPG = TILE_R / NRG;
    constexpr int NRP = RPG / 2;
    static_assert(NRP >= 1, "geometry");

    const int t     = threadIdx.x;
    const int o4    = t & (NO - 1);
    const int rg    = t / NO;
    const int obase = o4 * OPT;
    const int rbase = rg * RPG;

    u64 acc[NRP][DIM][OPT];
    #pragma unroll
    for (int p = 0; p < NRP; p++)
        #pragma unroll
        for (int i = 0; i < DIM; i++)
            #pragma unroll
            for (int j = 0; j < OPT; j++) acc[p][i][j] = 0ull;

    const unsigned xsa = (unsigned)__cvta_generic_to_shared(xs) + rbase * 4u;
    const unsigned wsa = (unsigned)__cvta_generic_to_shared(wsm) + obase * 4u;

    #pragma unroll 2
    for (int m = 0; m < MUL; m++) {
        u64 w2[OPT];
        #pragma unroll
        for (int q = 0; q < OPT / 4; q++) {
            const float4 wv = lds128(wsa + (unsigned)(m * MUL + 4 * q) * 4u);
            w2[4 * q + 0] = pack2(wv.x); w2[4 * q + 1] = pack2(wv.y);
            w2[4 * q + 2] = pack2(wv.z); w2[4 * q + 3] = pack2(wv.w);
        }
        #pragma unroll
        for (int i = 0; i < DIM; i++) {
            const unsigned a0 = xsa + (unsigned)((m * DIM + i) * RPAD) * 4u;
            #pragma unroll
            for (int p = 0; p < NRP; p++) {
                const u64 x2 = lds64(a0 + 8u * p);
                #pragma unroll
                for (int j = 0; j < OPT; j++)
                    acc[p][i][j] = fma2(x2, w2[j], acc[p][i][j]);
            }
        }
    }

    // ---- epilogue: unpack pairs (already scaled), coalesced float4 stores ----
    float* yt = y + (size_t)row0 * CH + obase * DIM;
    #pragma unroll
    for (int p = 0; p < NRP; p++) {
        const int r0 = rbase + 2 * p;
        float b0[OPT * DIM], b1[OPT * DIM];
        #pragma unroll
        for (int i = 0; i < DIM; i++)
            #pragma unroll
            for (int j = 0; j < OPT; j++) {
                float lo, hi;
                unpack2(acc[p][i][j], lo, hi);
                b0[j * DIM + i] = lo;
                b1[j * DIM + i] = hi;
            }
        if (r0 < nrows) {
            float* dst = yt + (size_t)r0 * CH;
            #pragma unroll
            for (int q = 0; q < OPT * DIM / 4; q++)
                *reinterpret_cast<float4*>(dst + 4 * q) =
                    make_float4(b0[4 * q], b0[4 * q + 1], b0[4 * q + 2], b0[4 * q + 3]);
        }
        if (r0 + 1 < nrows) {
            float* dst = yt + (size_t)(r0 + 1) * CH;
            #pragma unroll
            for (int q = 0; q < OPT * DIM / 4; q++)
                *reinterpret_cast<float4*>(dst + 4 * q) =
                    make_float4(b1[4 * q], b1[4 * q + 1], b1[4 * q + 2], b1[4 * q + 3]);
        }
    }
}

// dynamic smem: max over irreps of (CH*RPAD + MUL*MUL) floats
// irrep0: (128*66 + 16384)*4 = 99328 B  (the max)
#define SMEM_BYTES 99328

__global__ __launch_bounds__(TPB, 2)
void lin_main(const float* __restrict__ x0, const float* __restrict__ x1,
              const float* __restrict__ x2, const float* __restrict__ w,
              float* __restrict__ out) {
    extern __shared__ float xs[];
    const int b    = blockIdx.x;
    const int irr  = b % 3;                // interleave heavy/light tiles
    const int tile = b / 3;
    if (irr == 0) {
        // 128x0e: coeff = 1/(8*sqrt(128))
        run_irrep<128, 1, 8, 0>(x0, w, out, tile, 0.011048543456039806f, xs);
    } else if (irr == 1) {
        // 64x1o: coeff = 1/64
        run_irrep<64, 3, 4, 16384>(x1, w, out + (size_t)NELEM * 128,
                                   tile, 0.015625f, xs);
    } else {
        // 32x2e: coeff = 1/(8*sqrt(32))
        run_irrep<32, 5, 4, 20480>(x2, w, out + (size_t)NELEM * (128 + 192),
                                   tile, 0.022097086912079613f, xs);
    }
}

extern "C" void kernel_launch(void* const* d_in, const int* in_sizes, int n_in,
                              void* d_out, int out_size) {
    const float* x0     = (const float*)d_in[0];
    const float* x1     = (const float*)d_in[1];
    const float* x2     = (const float*)d_in[2];
    const float* w      = (const float*)d_in[3];
    const int*   counts = (const int*)d_in[4];
    float*       out    = (float*)d_out;

    cudaFuncSetAttribute(lin_main, cudaFuncAttributeMaxDynamicSharedMemorySize,
                         SMEM_BYTES);
    seg_kernel<<<1, NSEG>>>(counts);
    lin_main<<<3 * MAX_TILES, TPB, SMEM_BYTES>>>(x0, x1, x2, w, out);
}

// round 6
// speedup vs baseline: 1.2021x; 1.2021x over previous
#include <cuda_runtime.h>
#include <cstdint>

#define W_DIM   21504
#define NSEG    64
#define NELEM   8192
#define TILE_R  64
#define MAX_TILES 192     // sum(ceil(c/64)) <= 8192/64 + 64 = 192
#define TPB     256
#define RPAD    68        // row-dim stride in smem floats; %4==0 for 16B lds

typedef unsigned long long u64;

// ---------------- device globals ----------------
__device__ int  d_starts[NSEG + 1];
__device__ int2 d_tiles[MAX_TILES];   // {row_start, segment}
__device__ int  d_ntiles;

// ---------------- packed f32x2 helpers ----------------
__device__ __forceinline__ u64 pack2(float a) {
    u64 r; asm("mov.b64 %0, {%1, %1};" : "=l"(r) : "f"(a)); return r;
}
__device__ __forceinline__ u64 fma2(u64 a, u64 b, u64 c) {
    u64 d; asm("fma.rn.f32x2 %0, %1, %2, %3;" : "=l"(d) : "l"(a), "l"(b), "l"(c));
    return d;
}
__device__ __forceinline__ float2 lds_f2(unsigned a) {
    float2 v;
    asm volatile("ld.shared.v2.f32 {%0,%1}, [%2];"
                 : "=f"(v.x), "=f"(v.y) : "r"(a));
    return v;
}
__device__ __forceinline__ void lds_2u64(unsigned a, u64& x, u64& y) {
    asm volatile("ld.shared.v2.b64 {%0,%1}, [%2];"
                 : "=l"(x), "=l"(y) : "r"(a));
}
__device__ __forceinline__ void unpack2(u64 v, float& lo, float& hi) {
    asm("mov.b64 {%0, %1}, %2;" : "=f"(lo), "=f"(hi) : "l"(v));
}

// ---------------- prekernel: parallel scan + tile list ----------------
__global__ void seg_kernel(const int* __restrict__ counts) {
    __shared__ int wsum[2], wtsum[2];
    const int t  = threadIdx.x;           // 64 threads
    const int c  = counts[t];
    const int nt = (c + TILE_R - 1) >> 6;
    int sc = c, st = nt;
    #pragma unroll
    for (int d = 1; d < 32; d <<= 1) {
        int a = __shfl_up_sync(0xffffffffu, sc, d);
        int b = __shfl_up_sync(0xffffffffu, st, d);
        if ((t & 31) >= d) { sc += a; st += b; }
    }
    if ((t & 31) == 31) { wsum[t >> 5] = sc; wtsum[t >> 5] = st; }
    __syncthreads();
    if (t >= 32) { sc += wsum[0]; st += wtsum[0]; }
    const int startc = sc - c;
    const int startt = st - nt;
    d_starts[t] = startc;
    if (t == NSEG - 1) { d_starts[NSEG] = sc; d_ntiles = st; }
    for (int k = 0; k < nt; k++)
        d_tiles[startt + k] = make_int2(startc + TILE_R * k, t);
}

// ---------------- main compute ----------------
// Per tile (64 rows, segment g): y[r,o,i] = sum_m x[r,m,i] * (coeff*w[g,WOFF+m*MUL+o])
// Geometry: each thread owns 2 adjacent o's and RPG=TILE_R/NRG rows (NRP f32x2
// row-pairs). Weight smem traffic amortized over NRP rows; x loads are
// warp-broadcast (same address across all lanes of a warp).
template <int MUL, int DIM, int WOFF>
__device__ __forceinline__ void run_irrep(const float* __restrict__ x,
                                          const float* __restrict__ w,
                                          float* __restrict__ y,
                                          int tile, float coeff,
                                          float* xs) {
    if (tile >= d_ntiles) return;
    const int2 tt  = d_tiles[tile];
    const int row0 = tt.x;
    const int g    = tt.y;
    int nrows = d_starts[g + 1] - row0;
    if (nrows > TILE_R) nrows = TILE_R;

    constexpr int CH = MUL * DIM;
    float* wsm = xs + CH * RPAD;

    // ---- stage x tile transposed to [channel][row] ----
    const float* xt = x + (size_t)row0 * CH;
    #pragma unroll 4
    for (int e = threadIdx.x; e < TILE_R * CH; e += TPB) {
        int r = e / CH;
        int c = e - r * CH;
        xs[c * RPAD + r] = (r < nrows) ? xt[e] : 0.f;
    }
    // ---- stage weight tile, pre-scaled by coeff ----
    const float4* wrow = reinterpret_cast<const float4*>(w + (size_t)g * W_DIM + WOFF);
    float4* wd = reinterpret_cast<float4*>(wsm);
    #pragma unroll 4
    for (int j = threadIdx.x; j < MUL * MUL / 4; j += TPB) {
        float4 v = wrow[j];
        wd[j] = make_float4(v.x * coeff, v.y * coeff, v.z * coeff, v.w * coeff);
    }
    __syncthreads();

    constexpr int NO  = MUL / 2;          // o-lane count (2 o's per thread)
    constexpr int NRG = TPB / NO;         // row groups
    constexpr int RPG = TILE_R / NRG;     // rows per thread
    constexpr int NRP = RPG / 2;          // f32x2 row pairs (even by construction)
    static_assert(NRP >= 2 && (NRP & 1) == 0, "geometry");

    const int t     = threadIdx.x;
    const int o4    = t & (NO - 1);
    const int rg    = t / NO;
    const int obase = o4 * 2;
    const int rbase = rg * RPG;

    u64 acc[NRP][DIM][2];
    #pragma unroll
    for (int p = 0; p < NRP; p++)
        #pragma unroll
        for (int i = 0; i < DIM; i++) { acc[p][i][0] = 0ull; acc[p][i][1] = 0ull; }

    const unsigned xsa = (unsigned)__cvta_generic_to_shared(xs) + rbase * 4u;
    const unsigned wsa = (unsigned)__cvta_generic_to_shared(wsm) + obase * 4u;

    #pragma unroll 2
    for (int m = 0; m < MUL; m++) {
        const float2 wv = lds_f2(wsa + (unsigned)(m * MUL) * 4u);
        const u64 w0 = pack2(wv.x);
        const u64 w1 = pack2(wv.y);
        #pragma unroll
        for (int i = 0; i < DIM; i++) {
            const unsigned a0 = xsa + (unsigned)((m * DIM + i) * RPAD) * 4u;
            #pragma unroll
            for (int q = 0; q < NRP / 2; q++) {
                u64 xa, xb;
                lds_2u64(a0 + 16u * q, xa, xb);   // 4 rows = 2 f32x2 pairs
                acc[2*q    ][i][0] = fma2(xa, w0, acc[2*q    ][i][0]);
                acc[2*q    ][i][1] = fma2(xa, w1, acc[2*q    ][i][1]);
                acc[2*q + 1][i][0] = fma2(xb, w0, acc[2*q + 1][i][0]);
                acc[2*q + 1][i][1] = fma2(xb, w1, acc[2*q + 1][i][1]);
            }
        }
    }

    // ---- epilogue: unpack pairs (already scaled), float2 stores ----
    float* yt = y + (size_t)row0 * CH + obase * DIM;
    #pragma unroll
    for (int p = 0; p < NRP; p++) {
        const int r0 = rbase + 2 * p;
        float b0[2 * DIM], b1[2 * DIM];
        #pragma unroll
        for (int i = 0; i < DIM; i++)
            #pragma unroll
            for (int j = 0; j < 2; j++) {
                float lo, hi;
                unpack2(acc[p][i][j], lo, hi);
                b0[j * DIM + i] = lo;
                b1[j * DIM + i] = hi;
            }
        if (r0 < nrows) {
            float2* dst = reinterpret_cast<float2*>(yt + (size_t)r0 * CH);
            #pragma unroll
            for (int q = 0; q < DIM; q++)
                dst[q] = make_float2(b0[2 * q], b0[2 * q + 1]);
        }
        if (r0 + 1 < nrows) {
            float2* dst = reinterpret_cast<float2*>(yt + (size_t)(r0 + 1) * CH);
            #pragma unroll
            for (int q = 0; q < DIM; q++)
                dst[q] = make_float2(b1[2 * q], b1[2 * q + 1]);
        }
    }
}

// dynamic smem: max over irreps of (CH*RPAD + MUL*MUL) floats
// irrep0: (128*68 + 16384)*4 = 100352 B (max)
#define SMEM_BYTES 100352

__global__ __launch_bounds__(TPB, 2)
void lin_main(const float* __restrict__ x0, const float* __restrict__ x1,
              const float* __restrict__ x2, const float* __restrict__ w,
              float* __restrict__ out) {
    extern __shared__ float xs[];
    const int b    = blockIdx.x;
    const int irr  = b % 3;                // interleave heavy/light tiles
    const int tile = b / 3;
    if (irr == 0) {
        // 128x0e: coeff = 1/(8*sqrt(128))
        run_irrep<128, 1, 0>(x0, w, out, tile, 0.011048543456039806f, xs);
    } else if (irr == 1) {
        // 64x1o: coeff = 1/64
        run_irrep<64, 3, 16384>(x1, w, out + (size_t)NELEM * 128,
                                tile, 0.015625f, xs);
    } else {
        // 32x2e: coeff = 1/(8*sqrt(32))
        run_irrep<32, 5, 20480>(x2, w, out + (size_t)NELEM * (128 + 192),
                                tile, 0.022097086912079613f, xs);
    }
}

extern "C" void kernel_launch(void* const* d_in, const int* in_sizes, int n_in,
                              void* d_out, int out_size) {
    const float* x0     = (const float*)d_in[0];
    const float* x1     = (const float*)d_in[1];
    const float* x2     = (const float*)d_in[2];
    const float* w      = (const float*)d_in[3];
    const int*   counts = (const int*)d_in[4];
    float*       out    = (float*)d_out;

    cudaFuncSetAttribute(lin_main, cudaFuncAttributeMaxDynamicSharedMemorySize,
                         SMEM_BYTES);
    seg_kernel<<<1, NSEG>>>(counts);
    lin_main<<<3 * MAX_TILES, TPB, SMEM_BYTES>>>(x0, x1, x2, w, out);
}

// round 7
// speedup vs baseline: 1.3724x; 1.1416x over previous
#include <cuda_runtime.h>
#include <cuda_bf16.h>
#include <cstdint>

#define W_DIM   21504
#define NSEG    64
#define NELEM   8192
#define TILE_R  64
#define MAX_TILES 192
#define TPB     256
#define WB_SEG  43008      // bf16 elems per segment in d_wb (= 2*W_DIM)

// ---------------- device globals ----------------
__device__ int  d_starts[NSEG + 1];
__device__ int2 d_tiles[MAX_TILES];
__device__ int  d_ntiles;
__device__ __align__(16) __nv_bfloat16 d_wb[NSEG * WB_SEG];  // 5.5 MB: [g][irrep][o][k'=2K] (hi|lo)

// ---------------- mma / ldmatrix wrappers ----------------
__device__ __forceinline__ void ldsm4(uint32_t* r, unsigned addr) {
    asm volatile("ldmatrix.sync.aligned.m8n8.x4.shared.b16 {%0,%1,%2,%3}, [%4];"
                 : "=r"(r[0]), "=r"(r[1]), "=r"(r[2]), "=r"(r[3]) : "r"(addr));
}
__device__ __forceinline__ void mma_bf16(float* c, const uint32_t* a,
                                         uint32_t b0, uint32_t b1) {
    asm volatile("mma.sync.aligned.m16n8k16.row.col.f32.bf16.bf16.f32 "
                 "{%0,%1,%2,%3}, {%4,%5,%6,%7}, {%8,%9}, {%0,%1,%2,%3};"
                 : "+f"(c[0]), "+f"(c[1]), "+f"(c[2]), "+f"(c[3])
                 : "r"(a[0]), "r"(a[1]), "r"(a[2]), "r"(a[3]), "r"(b0), "r"(b1));
}

// ---------------- prekernel 1: segment scan + tile list ----------------
__global__ void seg_kernel(const int* __restrict__ counts) {
    __shared__ int wsum[2], wtsum[2];
    const int t  = threadIdx.x;           // 64 threads
    const int c  = counts[t];
    const int nt = (c + TILE_R - 1) >> 6;
    int sc = c, st = nt;
    #pragma unroll
    for (int d = 1; d < 32; d <<= 1) {
        int a = __shfl_up_sync(0xffffffffu, sc, d);
        int b = __shfl_up_sync(0xffffffffu, st, d);
        if ((t & 31) >= d) { sc += a; st += b; }
    }
    if ((t & 31) == 31) { wsum[t >> 5] = sc; wtsum[t >> 5] = st; }
    __syncthreads();
    if (t >= 32) { sc += wsum[0]; st += wtsum[0]; }
    const int startc = sc - c;
    const int startt = st - nt;
    d_starts[t] = startc;
    if (t == NSEG - 1) { d_starts[NSEG] = sc; d_ntiles = st; }
    for (int k = 0; k < nt; k++)
        d_tiles[startt + k] = make_int2(startc + TILE_R * k, t);
}

// ---------------- prekernel 2: w -> transposed, scaled, bf16 hi/lo split ----
// dst row o: [ hi(k=0..K-1) | lo(k=0..K-1) ]  (k = input channel m)
__global__ void wconv_kernel(const float* __restrict__ w) {
    int b = blockIdx.x;                    // 64 * 21 blocks
    int g = b / 21;
    int t = b % 21;
    int irrep, mt, ot;
    if (t < 16)      { irrep = 0; mt = t / 4;        ot = t % 4; }
    else if (t < 20) { irrep = 1; mt = (t - 16) / 2; ot = (t - 16) % 2; }
    else             { irrep = 2; mt = 0;            ot = 0; }
    const int   MUL   = (irrep == 0) ? 128 : (irrep == 1) ? 64 : 32;
    const int   WOFF  = (irrep == 0) ? 0 : (irrep == 1) ? 16384 : 20480;
    const int   OBASE = (irrep == 0) ? 0 : (irrep == 1) ? 32768 : 40960;
    const float coeff = (irrep == 0) ? 0.011048543456039806f
                       : (irrep == 1) ? 0.015625f : 0.022097086912079613f;

    __shared__ float tile[32][33];
    int tx = threadIdx.x & 31, ty = threadIdx.x >> 5;   // 32 x 8
    const float* wp = w + (size_t)g * W_DIM + WOFF + (mt * 32) * MUL + ot * 32;
    #pragma unroll
    for (int r = ty; r < 32; r += 8)
        tile[r][tx] = wp[r * MUL + tx] * coeff;         // [m-local][o-local]
    __syncthreads();
    __nv_bfloat16* dst = d_wb + (size_t)g * WB_SEG + OBASE;
    #pragma unroll
    for (int r = ty; r < 32; r += 8) {
        int o = ot * 32 + r;
        int m = mt * 32 + tx;
        float v = tile[tx][r];
        __nv_bfloat16 h = __float2bfloat16(v);
        float lo = v - __bfloat162float(h);
        dst[(size_t)o * (2 * MUL) + m]       = h;
        dst[(size_t)o * (2 * MUL) + MUL + m] = __float2bfloat16(lo);
    }
}

// ---------------- main: bf16-split tensor-core GEMM per tile ----------------
// Tile = 64 rows of one segment g.  GEMM: M' = 64*DIM (rows x components),
// K = N = MUL.  A[m'=(r*DIM+i)][k=m] = x[r][m][i];  B = d_wb rows (pre-split).
// Warp grid 4x2: wm in [0,4) along M', nh in [0,2) along N.
template <int MUL, int DIM, int WOFF2>
__device__ __forceinline__ void run_irrep_mma(const float* __restrict__ x,
                                              float* __restrict__ y,
                                              int tile, __nv_bfloat16* sm) {
    constexpr int K   = MUL;
    constexpr int CH  = MUL * DIM;
    constexpr int MP  = 64 * DIM;          // M'
    constexpr int LD  = 2 * K + 8;         // smem row stride (bf16), bank-safe
    constexpr int WM  = DIM;               // mtiles per warp (MP/16/4)
    constexpr int NB  = MUL / 32;          // n16 blocks per warp (N/2/16)
    constexpr int KS  = MUL / 16;

    const int2 tt  = d_tiles[tile];
    const int row0 = tt.x;
    const int g    = tt.y;
    int nrows = d_starts[g + 1] - row0;
    if (nrows > TILE_R) nrows = TILE_R;

    __nv_bfloat16* As = sm;
    __nv_bfloat16* Bs = sm + MP * LD;

    // ---- stage A: load x (float4), split hi/lo, scatter to [(r*DIM+i)][m] ----
    const float* xt = x + (size_t)row0 * CH;
    constexpr int CH4 = CH / 4;
    for (int e = threadIdx.x; e < 64 * CH4; e += TPB) {
        int r  = e / CH4;
        int c0 = (e - r * CH4) * 4;
        float4 v = make_float4(0.f, 0.f, 0.f, 0.f);
        if (r < nrows) v = *reinterpret_cast<const float4*>(xt + r * CH + c0);
        float vv[4] = {v.x, v.y, v.z, v.w};
        #pragma unroll
        for (int j = 0; j < 4; j++) {
            int c = c0 + j;
            int m = c / DIM;
            int i = c - m * DIM;
            int row = r * DIM + i;
            __nv_bfloat16 h = __float2bfloat16(vv[j]);
            float lo = vv[j] - __bfloat162float(h);
            As[row * LD + m]     = h;
            As[row * LD + K + m] = __float2bfloat16(lo);
        }
    }
    // ---- stage B: 16B copy of pre-split weights, insert row pad ----
    const uint4* src = reinterpret_cast<const uint4*>(d_wb + (size_t)g * WB_SEG + WOFF2);
    for (int j = threadIdx.x; j < MUL * (K / 4); j += TPB) {
        int row = j / (K / 4);
        int c   = j - row * (K / 4);
        *reinterpret_cast<uint4*>(&Bs[row * LD + c * 8]) = src[j];
    }
    __syncthreads();

    const int l  = threadIdx.x & 31;
    const int wp = threadIdx.x >> 5;
    const int wm = wp & 3, nh = wp >> 2;

    const unsigned sbase = (unsigned)__cvta_generic_to_shared(sm);
    const unsigned Abase = sbase;
    const unsigned Bbase = sbase + MP * LD * 2;
    const unsigned a_lane = ((l & 15) * LD + ((l >> 4) << 3)) * 2u;
    const unsigned b_lane = ((((l >> 4) & 1) * 8 + (l & 7)) * LD + (((l >> 3) & 1) << 3)) * 2u;

    float acc[WM][NB][2][4];
    #pragma unroll
    for (int mt = 0; mt < WM; mt++)
        #pragma unroll
        for (int nb = 0; nb < NB; nb++)
            #pragma unroll
            for (int h = 0; h < 2; h++)
                #pragma unroll
                for (int q = 0; q < 4; q++) acc[mt][nb][h][q] = 0.f;

    for (int ks = 0; ks < KS; ks++) {
        uint32_t af[WM][2][4];
        #pragma unroll
        for (int mt = 0; mt < WM; mt++) {
            unsigned ab = Abase + (unsigned)(((wm * WM + mt) * 16) * LD) * 2u
                        + (unsigned)ks * 32u + a_lane;
            ldsm4(af[mt][0], ab);
            ldsm4(af[mt][1], ab + K * 2u);
        }
        #pragma unroll
        for (int nb = 0; nb < NB; nb++) {
            unsigned bb = Bbase + (unsigned)((nh * (MUL / 2) + nb * 16) * LD) * 2u
                        + (unsigned)ks * 32u + b_lane;
            uint32_t bh[4], bl[4];
            ldsm4(bh, bb);
            ldsm4(bl, bb + K * 2u);
            #pragma unroll
            for (int mt = 0; mt < WM; mt++) {
                mma_bf16(acc[mt][nb][0], af[mt][0], bh[0], bh[1]);  // xh*wh
                mma_bf16(acc[mt][nb][1], af[mt][0], bh[2], bh[3]);
                mma_bf16(acc[mt][nb][0], af[mt][0], bl[0], bl[1]);  // xh*wl
                mma_bf16(acc[mt][nb][1], af[mt][0], bl[2], bl[3]);
                mma_bf16(acc[mt][nb][0], af[mt][1], bh[0], bh[1]);  // xl*wh
                mma_bf16(acc[mt][nb][1], af[mt][1], bh[2], bh[3]);
            }
        }
    }

    // ---- epilogue: C[(r,i)][o] -> y[r][o*DIM + i] ----
    float* yt = y + (size_t)row0 * CH;
    #pragma unroll
    for (int mt = 0; mt < WM; mt++) {
        const int mrow0 = (wm * WM + mt) * 16 + (l >> 2);
        #pragma unroll
        for (int nb = 0; nb < NB; nb++) {
            #pragma unroll
            for (int h8 = 0; h8 < 2; h8++) {
                const int n0 = nh * (MUL / 2) + nb * 16 + h8 * 8 + (l & 3) * 2;
                #pragma unroll
                for (int rr = 0; rr < 2; rr++) {
                    const int mrow = mrow0 + rr * 8;
                    const int r = mrow / DIM;
                    const int i = mrow - r * DIM;
                    if (r < nrows) {
                        const float v0 = acc[mt][nb][h8][rr * 2 + 0];
                        const float v1 = acc[mt][nb][h8][rr * 2 + 1];
                        if (DIM == 1) {
                            *reinterpret_cast<float2*>(&yt[(size_t)r * CH + n0]) =
                                make_float2(v0, v1);
                        } else {
                            yt[(size_t)r * CH + n0 * DIM + i]       = v0;
                            yt[(size_t)r * CH + (n0 + 1) * DIM + i] = v1;
                        }
                    }
                }
            }
        }
    }
}

// smem: max over irreps of (MP + MUL)*LD bf16:
//   irrep0: (64+128)*264*2 = 101376 B (max); irrep1: 69632; irrep2: 50688
#define SMEM_BYTES 101376

__global__ __launch_bounds__(TPB)
void lin_main(const float* __restrict__ x0, const float* __restrict__ x1,
              const float* __restrict__ x2, float* __restrict__ out) {
    extern __shared__ __nv_bfloat16 smem_bf[];
    const int b    = blockIdx.x;
    const int irr  = b % 3;
    const int tile = b / 3;
    if (tile >= d_ntiles) return;
    if (irr == 0) {
        run_irrep_mma<128, 1, 0>(x0, out, tile, smem_bf);
    } else if (irr == 1) {
        run_irrep_mma<64, 3, 32768>(x1, out + (size_t)NELEM * 128, tile, smem_bf);
    } else {
        run_irrep_mma<32, 5, 40960>(x2, out + (size_t)NELEM * (128 + 192), tile, smem_bf);
    }
}

extern "C" void kernel_launch(void* const* d_in, const int* in_sizes, int n_in,
                              void* d_out, int out_size) {
    const float* x0     = (const float*)d_in[0];
    const float* x1     = (const float*)d_in[1];
    const float* x2     = (const float*)d_in[2];
    const float* w      = (const float*)d_in[3];
    const int*   counts = (const int*)d_in[4];
    float*       out    = (float*)d_out;

    cudaFuncSetAttribute(lin_main, cudaFuncAttributeMaxDynamicSharedMemorySize,
                         SMEM_BYTES);
    seg_kernel<<<1, NSEG>>>(counts);
    wconv_kernel<<<NSEG * 21, 256>>>(w);
    lin_main<<<3 * MAX_TILES, TPB, SMEM_BYTES>>>(x0, x1, x2, out);
}

// round 8
// speedup vs baseline: 1.5702x; 1.1441x over previous
#include <cuda_runtime.h>
#include <cuda_bf16.h>
#include <cstdint>

#define W_DIM   21504
#define NSEG    64
#define NELEM   8192
#define TILE_R  64
#define MAX_TILES 192
#define TPB     256
#define WB_SEG  43008      // bf16 elems per segment in d_wb (= 2*W_DIM)
#define NWCONV  (NSEG * 21)

// ---------------- device globals ----------------
__device__ int  d_starts[NSEG + 1];
__device__ int2 d_tiles[MAX_TILES];
__device__ int  d_ntiles;
__device__ __align__(16) __nv_bfloat16 d_wb[NSEG * WB_SEG];  // [g][irrep][o][hi(K)|lo(K)]

// ---------------- mma / ldmatrix wrappers ----------------
__device__ __forceinline__ void ldsm4(uint32_t* r, unsigned addr) {
    asm volatile("ldmatrix.sync.aligned.m8n8.x4.shared.b16 {%0,%1,%2,%3}, [%4];"
                 : "=r"(r[0]), "=r"(r[1]), "=r"(r[2]), "=r"(r[3]) : "r"(addr));
}
__device__ __forceinline__ void mma_bf16(float* c, const uint32_t* a,
                                         uint32_t b0, uint32_t b1) {
    asm volatile("mma.sync.aligned.m16n8k16.row.col.f32.bf16.bf16.f32 "
                 "{%0,%1,%2,%3}, {%4,%5,%6,%7}, {%8,%9}, {%0,%1,%2,%3};"
                 : "+f"(c[0]), "+f"(c[1]), "+f"(c[2]), "+f"(c[3])
                 : "r"(a[0]), "r"(a[1]), "r"(a[2]), "r"(a[3]), "r"(b0), "r"(b1));
}
__device__ __forceinline__ uint32_t bfpair(float a, float b) {
    __nv_bfloat162 p = __floats2bfloat162_rn(a, b);   // x=a (low), y=b (high)
    return *reinterpret_cast<uint32_t*>(&p);
}
__device__ __forceinline__ void sts_v2(unsigned addr, uint32_t a, uint32_t b) {
    asm volatile("st.shared.v2.b32 [%0], {%1,%2};" :: "r"(addr), "r"(a), "r"(b));
}

// ---------------- fused prekernel: wconv blocks + one scan block ------------
__global__ void pre_kernel(const int* __restrict__ counts,
                           const float* __restrict__ w) {
    if (blockIdx.x == NWCONV) {
        // ---- segment scan + tile list (threads 0..63 active) ----
        __shared__ int wsum[2], wtsum[2];
        const int t = threadIdx.x;
        int c = 0, nt = 0, sc = 0, st = 0;
        if (t < 64) {
            c  = counts[t];
            nt = (c + TILE_R - 1) >> 6;
            sc = c; st = nt;
            #pragma unroll
            for (int d = 1; d < 32; d <<= 1) {
                int a = __shfl_up_sync(0xffffffffu, sc, d);
                int b = __shfl_up_sync(0xffffffffu, st, d);
                if ((t & 31) >= d) { sc += a; st += b; }
            }
            if ((t & 31) == 31) { wsum[t >> 5] = sc; wtsum[t >> 5] = st; }
        }
        __syncthreads();
        if (t < 64) {
            if (t >= 32) { sc += wsum[0]; st += wtsum[0]; }
            const int startc = sc - c;
            const int startt = st - nt;
            d_starts[t] = startc;
            if (t == 63) { d_starts[NSEG] = sc; d_ntiles = st; }
            for (int k = 0; k < nt; k++)
                d_tiles[startt + k] = make_int2(startc + TILE_R * k, t);
        }
        return;
    }
    // ---- weight convert: transpose, scale, bf16 hi/lo split ----
    int b = blockIdx.x;
    int g = b / 21;
    int t = b % 21;
    int irrep, mt, ot;
    if (t < 16)      { irrep = 0; mt = t / 4;        ot = t % 4; }
    else if (t < 20) { irrep = 1; mt = (t - 16) / 2; ot = (t - 16) % 2; }
    else             { irrep = 2; mt = 0;            ot = 0; }
    const int   MUL   = (irrep == 0) ? 128 : (irrep == 1) ? 64 : 32;
    const int   WOFF  = (irrep == 0) ? 0 : (irrep == 1) ? 16384 : 20480;
    const int   OBASE = (irrep == 0) ? 0 : (irrep == 1) ? 32768 : 40960;
    const float coeff = (irrep == 0) ? 0.011048543456039806f
                       : (irrep == 1) ? 0.015625f : 0.022097086912079613f;

    __shared__ float tile[32][33];
    int tx = threadIdx.x & 31, ty = threadIdx.x >> 5;   // 32 x 8
    const float* wp = w + (size_t)g * W_DIM + WOFF + (mt * 32) * MUL + ot * 32;
    #pragma unroll
    for (int r = ty; r < 32; r += 8)
        tile[r][tx] = wp[r * MUL + tx] * coeff;         // [m-local][o-local]
    __syncthreads();
    __nv_bfloat16* dst = d_wb + (size_t)g * WB_SEG + OBASE;
    #pragma unroll
    for (int r = ty; r < 32; r += 8) {
        int o = ot * 32 + r;
        int m = mt * 32 + tx;
        float v = tile[tx][r];
        __nv_bfloat16 h = __float2bfloat16(v);
        float lo = v - __bfloat162float(h);
        dst[(size_t)o * (2 * MUL) + m]       = h;
        dst[(size_t)o * (2 * MUL) + MUL + m] = __float2bfloat16(lo);
    }
}

// ---------------- main: bf16-split tensor-core GEMM per tile ----------------
// Tile = 64 rows of segment g.  GEMM: M' = 64*DIM, K = N = MUL.
// A[(r*DIM+i)][m] = x[r][m][i];  B rows = d_wb (pre-transposed/scaled/split).
template <int MUL, int DIM, int WOFF2>
__device__ __forceinline__ void run_irrep_mma(const float* __restrict__ x,
                                              float* __restrict__ y,
                                              int tile, __nv_bfloat16* sm) {
    constexpr int K   = MUL;
    constexpr int CH  = MUL * DIM;
    constexpr int MP  = 64 * DIM;
    constexpr int LD  = 2 * K + 8;
    constexpr int WM  = DIM;
    constexpr int NB  = MUL / 32;
    constexpr int KS  = MUL / 16;

    const int2 tt  = d_tiles[tile];
    const int row0 = tt.x;
    const int g    = tt.y;
    int nrows = d_starts[g + 1] - row0;
    if (nrows > TILE_R) nrows = TILE_R;

    __nv_bfloat16* As = sm;
    __nv_bfloat16* Bs = sm + MP * LD;
    const unsigned sbase = (unsigned)__cvta_generic_to_shared(sm);

    // ---- stage A: load float4, split hi/lo ----
    const float* xt = x + (size_t)row0 * CH;
    constexpr int CH4 = CH / 4;
    if (DIM == 1) {
        // packed path: row == r, cols m..m+3 contiguous -> v2.b32 stores
        for (int e = threadIdx.x; e < 64 * CH4; e += TPB) {
            int r  = e / CH4;
            int c0 = (e - r * CH4) * 4;
            float4 v = make_float4(0.f, 0.f, 0.f, 0.f);
            if (r < nrows) v = *reinterpret_cast<const float4*>(xt + r * CH + c0);
            float hx = __bfloat162float(__float2bfloat16(v.x));
            float hy = __bfloat162float(__float2bfloat16(v.y));
            float hz = __bfloat162float(__float2bfloat16(v.z));
            float hw = __bfloat162float(__float2bfloat16(v.w));
            unsigned ab = sbase + (unsigned)(r * LD + c0) * 2u;
            sts_v2(ab,           bfpair(v.x, v.y),           bfpair(v.z, v.w));
            sts_v2(ab + 2u * K,  bfpair(v.x - hx, v.y - hy), bfpair(v.z - hz, v.w - hw));
        }
    } else {
        for (int e = threadIdx.x; e < 64 * CH4; e += TPB) {
            int r  = e / CH4;
            int c0 = (e - r * CH4) * 4;
            float4 v = make_float4(0.f, 0.f, 0.f, 0.f);
            if (r < nrows) v = *reinterpret_cast<const float4*>(xt + r * CH + c0);
            float vv[4] = {v.x, v.y, v.z, v.w};
            #pragma unroll
            for (int j = 0; j < 4; j++) {
                int c = c0 + j;
                int m = c / DIM;
                int i = c - m * DIM;
                int row = r * DIM + i;
                __nv_bfloat16 h = __float2bfloat16(vv[j]);
                float lo = vv[j] - __bfloat162float(h);
                As[row * LD + m]     = h;
                As[row * LD + K + m] = __float2bfloat16(lo);
            }
        }
    }
    // ---- stage B: 16B copies of pre-split weights ----
    const uint4* src = reinterpret_cast<const uint4*>(d_wb + (size_t)g * WB_SEG + WOFF2);
    #pragma unroll 4
    for (int j = threadIdx.x; j < MUL * (K / 4); j += TPB) {
        int row = j / (K / 4);
        int c   = j - row * (K / 4);
        *reinterpret_cast<uint4*>(&Bs[row * LD + c * 8]) = src[j];
    }
    __syncthreads();

    const int l  = threadIdx.x & 31;
    const int wp = threadIdx.x >> 5;
    const int wm = wp & 3, nh = wp >> 2;

    const unsigned Abase = sbase;
    const unsigned Bbase = sbase + MP * LD * 2;
    const unsigned a_lane = ((l & 15) * LD + ((l >> 4) << 3)) * 2u;
    const unsigned b_lane = ((((l >> 4) & 1) * 8 + (l & 7)) * LD + (((l >> 3) & 1) << 3)) * 2u;

    float acc[WM][NB][2][4];
    #pragma unroll
    for (int mt = 0; mt < WM; mt++)
        #pragma unroll
        for (int nb = 0; nb < NB; nb++)
            #pragma unroll
            for (int h = 0; h < 2; h++)
                #pragma unroll
                for (int q = 0; q < 4; q++) acc[mt][nb][h][q] = 0.f;

    for (int ks = 0; ks < KS; ks++) {
        uint32_t af[WM][2][4];
        #pragma unroll
        for (int mt = 0; mt < WM; mt++) {
            unsigned ab = Abase + (unsigned)(((wm * WM + mt) * 16) * LD) * 2u
                        + (unsigned)ks * 32u + a_lane;
            ldsm4(af[mt][0], ab);
            ldsm4(af[mt][1], ab + K * 2u);
        }
        #pragma unroll
        for (int nb = 0; nb < NB; nb++) {
            unsigned bb = Bbase + (unsigned)((nh * (MUL / 2) + nb * 16) * LD) * 2u
                        + (unsigned)ks * 32u + b_lane;
            uint32_t bh[4], bl[4];
            ldsm4(bh, bb);
            ldsm4(bl, bb + K * 2u);
            #pragma unroll
            for (int mt = 0; mt < WM; mt++) {
                mma_bf16(acc[mt][nb][0], af[mt][0], bh[0], bh[1]);  // xh*wh
                mma_bf16(acc[mt][nb][1], af[mt][0], bh[2], bh[3]);
                mma_bf16(acc[mt][nb][0], af[mt][0], bl[0], bl[1]);  // xh*wl
                mma_bf16(acc[mt][nb][1], af[mt][0], bl[2], bl[3]);
                mma_bf16(acc[mt][nb][0], af[mt][1], bh[0], bh[1]);  // xl*wh
                mma_bf16(acc[mt][nb][1], af[mt][1], bh[2], bh[3]);
            }
        }
    }

    // ---- epilogue: C[(r,i)][o] -> y[r][o*DIM + i] ----
    float* yt = y + (size_t)row0 * CH;
    #pragma unroll
    for (int mt = 0; mt < WM; mt++) {
        const int mrow0 = (wm * WM + mt) * 16 + (l >> 2);
        #pragma unroll
        for (int nb = 0; nb < NB; nb++) {
            #pragma unroll
            for (int h8 = 0; h8 < 2; h8++) {
                const int n0 = nh * (MUL / 2) + nb * 16 + h8 * 8 + (l & 3) * 2;
                #pragma unroll
                for (int rr = 0; rr < 2; rr++) {
                    const int mrow = mrow0 + rr * 8;
                    const int r = mrow / DIM;
                    const int i = mrow - r * DIM;
                    if (r < nrows) {
                        const float v0 = acc[mt][nb][h8][rr * 2 + 0];
                        const float v1 = acc[mt][nb][h8][rr * 2 + 1];
                        if (DIM == 1) {
                            *reinterpret_cast<float2*>(&yt[(size_t)r * CH + n0]) =
                                make_float2(v0, v1);
                        } else {
                            yt[(size_t)r * CH + n0 * DIM + i]       = v0;
                            yt[(size_t)r * CH + (n0 + 1) * DIM + i] = v1;
                        }
                    }
                }
            }
        }
    }
}

// smem: irrep0 max: (64+128)*264*2 = 101376 B
#define SMEM_BYTES 101376

__global__ __launch_bounds__(TPB, 2)
void lin_main(const float* __restrict__ x0, const float* __restrict__ x1,
              const float* __restrict__ x2, float* __restrict__ out) {
    extern __shared__ __nv_bfloat16 smem_bf[];
    const int b    = blockIdx.x;
    const int irr  = b % 3;
    const int tile = b / 3;
    if (tile >= d_ntiles) return;
    if (irr == 0) {
        run_irrep_mma<128, 1, 0>(x0, out, tile, smem_bf);
    } else if (irr == 1) {
        run_irrep_mma<64, 3, 32768>(x1, out + (size_t)NELEM * 128, tile, smem_bf);
    } else {
        run_irrep_mma<32, 5, 40960>(x2, out + (size_t)NELEM * (128 + 192), tile, smem_bf);
    }
}

extern "C" void kernel_launch(void* const* d_in, const int* in_sizes, int n_in,
                              void* d_out, int out_size) {
    const float* x0     = (const float*)d_in[0];
    const float* x1     = (const float*)d_in[1];
    const float* x2     = (const float*)d_in[2];
    const float* w      = (const float*)d_in[3];
    const int*   counts = (const int*)d_in[4];
    float*       out    = (float*)d_out;

    cudaFuncSetAttribute(lin_main, cudaFuncAttributeMaxDynamicSharedMemorySize,
                         SMEM_BYTES);
    pre_kernel<<<NWCONV + 1, 256>>>(counts, w);
    lin_main<<<3 * MAX_TILES, TPB, SMEM_BYTES>>>(x0, x1, x2, out);
}